// round 7
// baseline (speedup 1.0000x reference)
#include <cuda_runtime.h>
#include <math.h>

#define BB 16384
#define CC 8192

// ---------------- device scratch (no runtime allocation) ----------------
__device__ int   d_first[CC];          // first occurrence row per label (BB if absent)
__device__ int   d_cnt[CC];            // count per label
__device__ int   d_hist[64 * CC];      // per-256-row-block histograms -> exclusive block prefix
__device__ int   d_start[BB];          // exclusive scan of group sizes (keyed by first-occ row)
__device__ int   d_rank[BB];           // stable rank within 256-row block (same label)
__device__ int   d_lab[BB];            // normalized int32 labels
__device__ float d_loss[BB];           // per-row loss
__device__ unsigned int d_ticket;      // last-block election
__device__ int   d_init, d_cdone, d_ready;   // prep stage flags (reset by final block)

__global__ void __launch_bounds__(256, 8)
k_all(const float* __restrict__ logits, const void* __restrict__ labels,
      float* __restrict__ out, long long osz)
{
    const int row = blockIdx.x;
    const int t = threadIdx.x;

    __shared__ unsigned short srun[CC];   // 16KB: count-stage running histogram
    __shared__ int ssum[256];
    __shared__ float red[8];
    __shared__ double sd[256];
    __shared__ unsigned int s_last;
    __shared__ int s_is64;

    // ================= prep roles (blocks 0..128, all wave-1 resident) =================
    if (row < 129) {
        if (row == 0) {
            for (int k = t; k < CC; k += 256) { d_first[k] = BB; d_cnt[k] = 0; }
            __threadfence();
            __syncthreads();
            if (t == 0) atomicExch(&d_init, 1);
        }
        if (row < 64) {
            if (t == 0) { while (atomicAdd(&d_init, 0) < 1) __nanosleep(32); }
            __syncthreads();
            // label width detection on a word range valid for both int32/int64
            {
                const int* w = (const int*)labels;
                int p = (row & 31) * 256 + t;           // p < 8192 -> word 2p+1 <= 16383
                int any = __syncthreads_or(w[2 * p + 1] != 0);
                if (t == 0) s_is64 = !any;              // all odd words zero -> int64
            }
            for (int k = t; k < CC; k += 256) srun[k] = 0;
            __syncthreads();
            const int i = row * 256 + t;
            const int lab = s_is64 ? (int)((const long long*)labels)[i]
                                   : ((const int*)labels)[i];
            d_lab[i] = lab;
            atomicMin(&d_first[lab], i);
            atomicAdd(&d_cnt[lab], 1);
            // stable in-block rank via warp-ordered phases (no smem atomics: u16)
            const int l = t & 31, w = t >> 5;
            unsigned eq = 0u;
#pragma unroll
            for (int j = 0; j < 32; j++) {
                int lj = __shfl_sync(0xffffffffu, lab, j);
                eq |= (unsigned)(lj == lab) << j;
            }
            const int before  = __popc(eq & ((1u << l) - 1u));
            const int total   = __popc(eq);
            const bool is_last = (31 - __clz(eq)) == l;
            int rank = 0;
            for (int ph = 0; ph < 8; ph++) {
                if (w == ph) {
                    rank = (int)srun[lab] + before;
                    __syncwarp();
                    if (is_last) srun[lab] = (unsigned short)((int)srun[lab] + total);
                }
                __syncthreads();
            }
            d_rank[i] = rank;
            for (int k = t; k < CC; k += 256) d_hist[row * CC + k] = (int)srun[k];
            __threadfence();
            __syncthreads();
            if (t == 0) atomicAdd(&d_cdone, 1);
        } else if (row == 64) {
            // group-start scan (exclusive scan of group sizes keyed by first-occ row)
            if (t == 0) { while (atomicAdd(&d_cdone, 0) < 64) __nanosleep(64); }
            __syncthreads();
            int acc = 0;
#pragma unroll 8
            for (int k = 0; k < 64; k++) {
                int r = t * 64 + k;
                int lab = __ldcg(&d_lab[r]);
                int fo  = __ldcg(&d_first[lab]);
                acc += (fo == r) ? __ldcg(&d_cnt[lab]) : 0;
            }
            ssum[t] = acc;
            __syncthreads();
            for (int off = 1; off < 256; off <<= 1) {
                int v = (t >= off) ? ssum[t - off] : 0;
                __syncthreads();
                ssum[t] += v;
                __syncthreads();
            }
            int run = (t == 0) ? 0 : ssum[t - 1];
#pragma unroll 8
            for (int k = 0; k < 64; k++) {
                int r = t * 64 + k;
                int lab = __ldcg(&d_lab[r]);
                int fo  = __ldcg(&d_first[lab]);
                int gv  = (fo == r) ? __ldcg(&d_cnt[lab]) : 0;
                d_start[r] = run;
                run += gv;
            }
            __threadfence();
            __syncthreads();
            if (t == 0) atomicAdd(&d_ready, 1);
        } else {
            // blocks 65..128: in-place exclusive prefix of d_hist along the 64-block axis,
            // one warp handles 16 labels (lane holds 2 block-values, warp shfl-scan)
            if (t == 0) { while (atomicAdd(&d_cdone, 0) < 64) __nanosleep(64); }
            __syncthreads();
            const int l = t & 31, w = t >> 5;
            const int base = (row - 65) * 128 + w * 16;
            for (int q = 0; q < 16; q++) {
                const int c = base + q;
                int v0 = __ldcg(&d_hist[(2 * l) * CC + c]);
                int v1 = __ldcg(&d_hist[(2 * l + 1) * CC + c]);
                int s = v0 + v1;
#pragma unroll
                for (int o = 1; o < 32; o <<= 1) {
                    int x = __shfl_up_sync(0xffffffffu, s, o);
                    if (l >= o) s += x;
                }
                int excl = s - (v0 + v1);
                d_hist[(2 * l) * CC + c] = excl;
                d_hist[(2 * l + 1) * CC + c] = excl + v0;
            }
            __threadfence();
            __syncthreads();
            if (t == 0) atomicAdd(&d_ready, 1);
        }
    }

    // ================= wait for all prep (scan + 64 prefix blocks) =================
    if (t == 0) { while (atomicAdd(&d_ready, 0) < 65) __nanosleep(64); }
    __syncthreads();

    // ================= main streaming body (R6) =================
    const int lab = __ldcg(&d_lab[row]);
    const int dst = __ldcg(&d_start[__ldcg(&d_first[lab])])
                  + __ldcg(&d_hist[(row >> 8) * CC + lab])
                  + __ldcg(&d_rank[row]);
    const float4* __restrict__ src = (const float4*)(logits + (size_t)row * CC);
    float4* __restrict__ o4 = (float4*)(out + (size_t)dst * CC);

    const int tgt4 = lab >> 2, tsub = lab & 3;
    const long long nbig = (long long)BB * CC;
    const bool do_store = (osz >= nbig);

    float s0 = 0.0f, s1 = 0.0f;
    float tval = 0.0f;
    bool have_t = false;

#pragma unroll
    for (int k = 0; k < 8; k++) {
        const int idx = k * 256 + t;
        float4 x = __ldcs(src + idx);
        if (idx == tgt4) {
            float vv = (tsub == 0) ? x.x : (tsub == 1) ? x.y : (tsub == 2) ? x.z : x.w;
            float nv = (vv > 0.0f) ? (vv / 2.00001f - 0.2f) : (vv * 2.00001f - 0.2f);
            if (tsub == 0) x.x = nv; else if (tsub == 1) x.y = nv;
            else if (tsub == 2) x.z = nv; else x.w = nv;
            tval = nv; have_t = true;
        }
        if (do_store) __stcs(o4 + idx, x);
        s0 += __expf(x.x) + __expf(x.y);
        s1 += __expf(x.z) + __expf(x.w);
    }

    float ws = s0 + s1;
#pragma unroll
    for (int o = 16; o; o >>= 1) ws += __shfl_xor_sync(0xffffffffu, ws, o);
    if ((t & 31) == 0) red[t >> 5] = ws;
    __syncthreads();
    if (t < 32) {
        float v = (t < 8) ? red[t] : 0.0f;
#pragma unroll
        for (int o = 4; o; o >>= 1) v += __shfl_xor_sync(0xffffffffu, v, o);
        if (t == 0) red[0] = v;
    }
    __syncthreads();
    const float s = red[0];

    if (have_t) d_loss[row] = __logf(s) - tval;
    __threadfence();                           // publish loss before ticket
    if (t == 0 && osz >= nbig + BB) out[(size_t)nbig + dst] = (float)lab;

    // ---- last block: deterministic loss reduction + flag reset for next replay ----
    __syncthreads();
    if (t == 0) s_last = atomicAdd(&d_ticket, 1u);
    __syncthreads();
    if (s_last == BB - 1) {
        __threadfence();
        double a = 0.0;
        const float4* lf = (const float4*)d_loss;
        for (int i = t; i < BB / 4; i += 256) {
            float4 v = __ldcg(lf + i);
            a += (double)v.x + (double)v.y + (double)v.z + (double)v.w;
        }
        sd[t] = a;
        __syncthreads();
        for (int o = 128; o; o >>= 1) {
            if (t < o) sd[t] += sd[t + o];
            __syncthreads();
        }
        if (t == 0) {
            float L = (float)(sd[0] / (double)BB);
            if (osz >= nbig + BB + 1)      out[(size_t)nbig + BB] = L;
            else if (osz == 1)             out[0] = L;
            // reset stage flags for the next graph replay (all blocks are past
            // their spins: every block already incremented d_ticket)
            d_init = 0; d_cdone = 0; d_ready = 0; d_ticket = 0u;
        }
    }
}

// ---------------- launch ----------------
extern "C" void kernel_launch(void* const* d_in, const int* in_sizes, int n_in,
                              void* d_out, int out_size) {
    const float* logits = (const float*)d_in[0];
    const void*  labels = d_in[1];
    float* out = (float*)d_out;
    long long osz = (long long)out_size;

    k_all<<<BB, 256>>>(logits, labels, out, osz);
}

// round 8
// speedup vs baseline: 1.0858x; 1.0858x over previous
#include <cuda_runtime.h>
#include <math.h>

#define BB 16384
#define CC 8192

// ---------------- device scratch (no runtime allocation) ----------------
__device__ int   d_first[CC];          // first occurrence row per label (BB if absent)
__device__ int   d_cnt[CC];            // count per label
__device__ int   d_hist[64 * CC];      // per-256-row-block histograms -> exclusive block prefix
__device__ int   d_start[BB];          // exclusive scan of group sizes (keyed by first-occ row)
__device__ int   d_rank[BB];           // stable rank within 256-row block (same label)
__device__ int   d_lab[BB];            // normalized int32 labels
__device__ float d_loss[BB];           // per-row loss
__device__ unsigned int d_ticket;      // last-block election in k_main
__device__ volatile int d_init;        // prep stage flag: init done
__device__ volatile int d_cdone;       // prep stage flag: count blocks done
__device__ int d_cdone_atomic[1];      // aliased via address for RMW (same var via cast not allowed; use separate counter)

// NOTE: use a dedicated atomic counter for count-done and mirror into the
// volatile flag is unnecessary complexity; instead poll the atomic counter
// with plain volatile reads through a cast.
__device__ int d_ccount;               // atomic count-done counter (polled via volatile read)

// ================= prep kernel: 129 blocks, internal spin staging =================
__global__ void __launch_bounds__(256)
k_prep(const void* __restrict__ labels)
{
    const int row = blockIdx.x;
    const int t = threadIdx.x;
    __shared__ unsigned short srun[CC];   // 16KB running block histogram
    __shared__ int ssum[256];
    __shared__ int s_is64;

    if (row == 0) {
        for (int k = t; k < CC; k += 256) { d_first[k] = BB; d_cnt[k] = 0; }
        __threadfence();
        __syncthreads();
        if (t == 0) d_init = 1;            // volatile store after fence
    }

    if (row < 64) {
        if (row != 0) {
            if (t == 0) { while (d_init == 0) __nanosleep(32); }
            __syncthreads();
        }
        // label width detection: int64 (LE) => all odd 32-bit words zero
        {
            const int* w = (const int*)labels;
            int p = (row & 31) * 256 + t;            // p < 8192, word 2p+1 <= 16383
            int any = __syncthreads_or(w[2 * p + 1] != 0);
            if (t == 0) s_is64 = !any;
        }
        for (int k = t; k < CC; k += 256) srun[k] = 0;
        __syncthreads();

        const int i = row * 256 + t;
        const int lab = s_is64 ? (int)((const long long*)labels)[i]
                               : ((const int*)labels)[i];
        d_lab[i] = lab;
        atomicMin(&d_first[lab], i);
        atomicAdd(&d_cnt[lab], 1);

        // stable in-block rank via warp-ordered phases
        const int l = t & 31, w = t >> 5;
        unsigned eq = 0u;
#pragma unroll
        for (int j = 0; j < 32; j++) {
            int lj = __shfl_sync(0xffffffffu, lab, j);
            eq |= (unsigned)(lj == lab) << j;
        }
        const int before  = __popc(eq & ((1u << l) - 1u));
        const int total   = __popc(eq);
        const bool is_last = (31 - __clz(eq)) == l;
        int rank = 0;
        for (int ph = 0; ph < 8; ph++) {
            if (w == ph) {
                rank = (int)srun[lab] + before;
                __syncwarp();
                if (is_last) srun[lab] = (unsigned short)((int)srun[lab] + total);
            }
            __syncthreads();
        }
        d_rank[i] = rank;
        for (int k = t; k < CC; k += 256) d_hist[row * CC + k] = (int)srun[k];
        __threadfence();
        __syncthreads();
        if (t == 0) atomicAdd(&d_ccount, 1);
    } else if (row == 64) {
        // group-start scan after all 64 count blocks
        if (t == 0) {
            while (*(volatile int*)&d_ccount < 64) __nanosleep(64);
        }
        __syncthreads();
        int acc = 0;
#pragma unroll 8
        for (int k = 0; k < 64; k++) {
            int r = t * 64 + k;
            int lab = __ldcg(&d_lab[r]);
            int fo  = __ldcg(&d_first[lab]);
            acc += (fo == r) ? __ldcg(&d_cnt[lab]) : 0;
        }
        ssum[t] = acc;
        __syncthreads();
        for (int off = 1; off < 256; off <<= 1) {
            int v = (t >= off) ? ssum[t - off] : 0;
            __syncthreads();
            ssum[t] += v;
            __syncthreads();
        }
        int run = (t == 0) ? 0 : ssum[t - 1];
#pragma unroll 8
        for (int k = 0; k < 64; k++) {
            int r = t * 64 + k;
            int lab = __ldcg(&d_lab[r]);
            int fo  = __ldcg(&d_first[lab]);
            int gv  = (fo == r) ? __ldcg(&d_cnt[lab]) : 0;
            d_start[r] = run;
            run += gv;
        }
    } else {
        // blocks 65..128: exclusive prefix of d_hist along the 64-block axis.
        // One warp scans 16 labels; lane holds 2 block-values (shfl scan).
        if (t == 0) {
            while (*(volatile int*)&d_ccount < 64) __nanosleep(64);
        }
        __syncthreads();
        const int l = t & 31, w = t >> 5;
        const int base = (row - 65) * 128 + w * 16;
        for (int q = 0; q < 16; q++) {
            const int c = base + q;
            int v0 = __ldcg(&d_hist[(2 * l) * CC + c]);
            int v1 = __ldcg(&d_hist[(2 * l + 1) * CC + c]);
            int s = v0 + v1;
#pragma unroll
            for (int o = 1; o < 32; o <<= 1) {
                int x = __shfl_up_sync(0xffffffffu, s, o);
                if (l >= o) s += x;
            }
            int excl = s - (v0 + v1);
            d_hist[(2 * l) * CC + c] = excl;
            d_hist[(2 * l + 1) * CC + c] = excl + v0;
        }
    }
}

// ================= main streaming kernel (R6 body, proven 183.5us) =================
__global__ void __launch_bounds__(256) k_main(const float* __restrict__ logits,
                                              float* __restrict__ out,
                                              long long osz) {
    const int row = blockIdx.x;
    const int t = threadIdx.x;
    const int lab = d_lab[row];
    const int dst = d_start[d_first[lab]] + d_hist[(row >> 8) * CC + lab] + d_rank[row];
    const float4* __restrict__ src = (const float4*)(logits + (size_t)row * CC);
    float4* __restrict__ o4 = (float4*)(out + (size_t)dst * CC);

    const int tgt4 = lab >> 2, tsub = lab & 3;
    const long long nbig = (long long)BB * CC;
    const bool do_store = (osz >= nbig);

    float s0 = 0.0f, s1 = 0.0f;
    float tval = 0.0f;
    bool have_t = false;

#pragma unroll
    for (int k = 0; k < 8; k++) {
        const int idx = k * 256 + t;
        float4 x = __ldcs(src + idx);
        if (idx == tgt4) {
            float vv = (tsub == 0) ? x.x : (tsub == 1) ? x.y : (tsub == 2) ? x.z : x.w;
            float nv = (vv > 0.0f) ? (vv / 2.00001f - 0.2f) : (vv * 2.00001f - 0.2f);
            if (tsub == 0) x.x = nv; else if (tsub == 1) x.y = nv;
            else if (tsub == 2) x.z = nv; else x.w = nv;
            tval = nv; have_t = true;
        }
        if (do_store) __stcs(o4 + idx, x);
        s0 += __expf(x.x) + __expf(x.y);
        s1 += __expf(x.z) + __expf(x.w);
    }

    __shared__ float red[8];
    float ws = s0 + s1;
#pragma unroll
    for (int o = 16; o; o >>= 1) ws += __shfl_xor_sync(0xffffffffu, ws, o);
    if ((t & 31) == 0) red[t >> 5] = ws;
    __syncthreads();
    if (t < 32) {
        float v = (t < 8) ? red[t] : 0.0f;
#pragma unroll
        for (int o = 4; o; o >>= 1) v += __shfl_xor_sync(0xffffffffu, v, o);
        if (t == 0) red[0] = v;
    }
    __syncthreads();
    const float s = red[0];

    if (have_t) {
        d_loss[row] = __logf(s) - tval;
        __threadfence();                       // publish loss before ticket
    }
    if (t == 0 && osz >= nbig + BB) out[(size_t)nbig + dst] = (float)lab;

    // ---- last block: deterministic loss reduction + flag reset for next replay ----
    __shared__ unsigned int s_last;
    __syncthreads();
    if (t == 0) s_last = atomicAdd(&d_ticket, 1u);
    __syncthreads();
    if (s_last == BB - 1) {
        __threadfence();
        __shared__ double sd[256];
        double a = 0.0;
        const float4* lf = (const float4*)d_loss;
        for (int i = t; i < BB / 4; i += 256) {
            float4 v = __ldcg(lf + i);
            a += (double)v.x + (double)v.y + (double)v.z + (double)v.w;
        }
        sd[t] = a;
        __syncthreads();
        for (int o = 128; o; o >>= 1) {
            if (t < o) sd[t] += sd[t + o];
            __syncthreads();
        }
        if (t == 0) {
            float L = (float)(sd[0] / (double)BB);
            if (osz >= nbig + BB + 1)      out[(size_t)nbig + BB] = L;
            else if (osz == 1)             out[0] = L;
            // reset prep flags for the next graph replay (prep kernel long done)
            d_init = 0; d_ccount = 0; d_ticket = 0u;
        }
    }
}

// ---------------- launch ----------------
extern "C" void kernel_launch(void* const* d_in, const int* in_sizes, int n_in,
                              void* d_out, int out_size) {
    const float* logits = (const float*)d_in[0];
    const void*  labels = d_in[1];
    float* out = (float*)d_out;
    long long osz = (long long)out_size;

    k_prep<<<129, 256>>>(labels);
    k_main<<<BB, 256>>>(logits, out, osz);
}

// round 9
// speedup vs baseline: 1.1704x; 1.0780x over previous
#include <cuda_runtime.h>
#include <math.h>

#define BB 16384
#define CC 8192

// ---------------- device scratch (no runtime allocation) ----------------
// d_first2/d_cnt are ZERO when idle; k_main's final block re-zeroes them for
// the next graph replay. d_first2[lab] = max over rows i with label lab of
// (BB - i)  =>  first occurrence = BB - d_first2[lab]; 0 = label absent.
__device__ int   d_first2[CC];
__device__ int   d_cnt[CC];
__device__ int   d_hist[64 * CC];      // per-256-row-block histograms -> excl. block prefix
__device__ int   d_start[BB];          // excl. scan of group sizes (keyed by first-occ row)
__device__ int   d_rank[BB];           // stable rank within 256-row block (same label)
__device__ int   d_lab[BB];            // normalized int32 labels
__device__ float d_loss[BB];           // per-row loss
__device__ unsigned int d_ticket;      // last-block election in k_main

// ================= k1: detect + convert + count + stable in-block rank =================
__global__ void __launch_bounds__(256) k1(const void* __restrict__ labels) {
    const int t = threadIdx.x, b = blockIdx.x;
    __shared__ unsigned short srun[CC];   // 16KB running block histogram
    __shared__ int s_is64;

    // label width detection: int64 (LE) => all odd 32-bit words zero.
    // p < 8192 keeps word index valid for the int32 case too.
    {
        const int* w = (const int*)labels;
        int p = (b & 31) * 256 + t;
        int any = __syncthreads_or(w[2 * p + 1] != 0);
        if (t == 0) s_is64 = !any;
    }
    for (int k = t; k < CC; k += 256) srun[k] = 0;
    __syncthreads();

    const int i = b * 256 + t;
    const int lab = s_is64 ? (int)((const long long*)labels)[i]
                           : ((const int*)labels)[i];
    d_lab[i] = lab;
    atomicMax(&d_first2[lab], BB - i);     // zero-init friendly "first occurrence"
    atomicAdd(&d_cnt[lab], 1);

    // stable in-block rank via warp-ordered phases (u16 smem, no atomics)
    const int l = t & 31, w = t >> 5;
    unsigned eq = 0u;
#pragma unroll
    for (int j = 0; j < 32; j++) {
        int lj = __shfl_sync(0xffffffffu, lab, j);
        eq |= (unsigned)(lj == lab) << j;
    }
    const int before  = __popc(eq & ((1u << l) - 1u));
    const int total   = __popc(eq);
    const bool is_last = (31 - __clz(eq)) == l;
    int rank = 0;
    for (int ph = 0; ph < 8; ph++) {
        if (w == ph) {
            rank = (int)srun[lab] + before;
            __syncwarp();
            if (is_last) srun[lab] = (unsigned short)((int)srun[lab] + total);
        }
        __syncthreads();
    }
    d_rank[i] = rank;
    for (int k = t; k < CC; k += 256) d_hist[b * CC + k] = (int)srun[k];
}

// ================= k2: group-start scan (block 64) + hist block-prefix (0-63) =================
__global__ void __launch_bounds__(256) k2() {
    const int t = threadIdx.x, b = blockIdx.x;
    if (b == 64) {
        __shared__ int ssum[256];
        int acc = 0;
#pragma unroll 8
        for (int k = 0; k < 64; k++) {
            int r = t * 64 + k;
            int lab = d_lab[r];
            acc += (BB - d_first2[lab] == r) ? d_cnt[lab] : 0;
        }
        ssum[t] = acc;
        __syncthreads();
        for (int off = 1; off < 256; off <<= 1) {
            int v = (t >= off) ? ssum[t - off] : 0;
            __syncthreads();
            ssum[t] += v;
            __syncthreads();
        }
        int run = (t == 0) ? 0 : ssum[t - 1];
#pragma unroll 8
        for (int k = 0; k < 64; k++) {
            int r = t * 64 + k;
            int lab = d_lab[r];
            int gv = (BB - d_first2[lab] == r) ? d_cnt[lab] : 0;
            d_start[r] = run;
            run += gv;
        }
    } else {
        // exclusive prefix of d_hist along the 64-block axis.
        // One warp scans 16 labels; each lane holds 2 block-values (shfl scan).
        const int l = t & 31, w = t >> 5;
        const int base = b * 128 + w * 16;
        for (int q = 0; q < 16; q++) {
            const int c = base + q;
            int v0 = d_hist[(2 * l) * CC + c];
            int v1 = d_hist[(2 * l + 1) * CC + c];
            int s = v0 + v1;
#pragma unroll
            for (int o = 1; o < 32; o <<= 1) {
                int x = __shfl_up_sync(0xffffffffu, s, o);
                if (l >= o) s += x;
            }
            int excl = s - (v0 + v1);
            d_hist[(2 * l) * CC + c] = excl;
            d_hist[(2 * l + 1) * CC + c] = excl + v0;
        }
    }
}

// ================= main streaming kernel (proven 182us body) =================
__global__ void __launch_bounds__(256) k_main(const float* __restrict__ logits,
                                              float* __restrict__ out,
                                              long long osz) {
    const int row = blockIdx.x;
    const int t = threadIdx.x;
    const int lab = d_lab[row];
    const int dst = d_start[BB - d_first2[lab]]
                  + d_hist[(row >> 8) * CC + lab] + d_rank[row];
    const float4* __restrict__ src = (const float4*)(logits + (size_t)row * CC);
    float4* __restrict__ o4 = (float4*)(out + (size_t)dst * CC);

    const int tgt4 = lab >> 2, tsub = lab & 3;
    const long long nbig = (long long)BB * CC;
    const bool do_store = (osz >= nbig);

    float s0 = 0.0f, s1 = 0.0f;
    float tval = 0.0f;
    bool have_t = false;

#pragma unroll
    for (int k = 0; k < 8; k++) {
        const int idx = k * 256 + t;
        float4 x = __ldcs(src + idx);
        if (idx == tgt4) {
            float vv = (tsub == 0) ? x.x : (tsub == 1) ? x.y : (tsub == 2) ? x.z : x.w;
            float nv = (vv > 0.0f) ? (vv / 2.00001f - 0.2f) : (vv * 2.00001f - 0.2f);
            if (tsub == 0) x.x = nv; else if (tsub == 1) x.y = nv;
            else if (tsub == 2) x.z = nv; else x.w = nv;
            tval = nv; have_t = true;
        }
        if (do_store) __stcs(o4 + idx, x);
        s0 += __expf(x.x) + __expf(x.y);
        s1 += __expf(x.z) + __expf(x.w);
    }

    __shared__ float red[8];
    float ws = s0 + s1;
#pragma unroll
    for (int o = 16; o; o >>= 1) ws += __shfl_xor_sync(0xffffffffu, ws, o);
    if ((t & 31) == 0) red[t >> 5] = ws;
    __syncthreads();
    if (t < 32) {
        float v = (t < 8) ? red[t] : 0.0f;
#pragma unroll
        for (int o = 4; o; o >>= 1) v += __shfl_xor_sync(0xffffffffu, v, o);
        if (t == 0) red[0] = v;
    }
    __syncthreads();
    const float s = red[0];

    if (have_t) {
        d_loss[row] = __logf(s) - tval;
        __threadfence();                       // publish loss before ticket
    }
    if (t == 0 && osz >= nbig + BB) out[(size_t)nbig + dst] = (float)lab;

    // ---- last block: deterministic loss reduction + scratch reset for next replay ----
    __shared__ unsigned int s_last;
    __syncthreads();
    if (t == 0) s_last = atomicAdd(&d_ticket, 1u);
    __syncthreads();
    if (s_last == BB - 1) {
        __threadfence();
        __shared__ double sd[256];
        double a = 0.0;
        const float4* lf = (const float4*)d_loss;
        for (int i = t; i < BB / 4; i += 256) {
            float4 v = __ldcg(lf + i);
            a += (double)v.x + (double)v.y + (double)v.z + (double)v.w;
        }
        sd[t] = a;
        __syncthreads();
        for (int o = 128; o; o >>= 1) {
            if (t < o) sd[t] += sd[t + o];
            __syncthreads();
        }
        if (t == 0) {
            float L = (float)(sd[0] / (double)BB);
            if (osz >= nbig + BB + 1)      out[(size_t)nbig + BB] = L;
            else if (osz == 1)             out[0] = L;
            d_ticket = 0u;
        }
        // zero d_first2/d_cnt for the next replay (all blocks already past
        // their reads: every block incremented d_ticket after computing dst)
        for (int k = t; k < CC; k += 256) { d_first2[k] = 0; d_cnt[k] = 0; }
    }
}

// ---------------- launch ----------------
extern "C" void kernel_launch(void* const* d_in, const int* in_sizes, int n_in,
                              void* d_out, int out_size) {
    const float* logits = (const float*)d_in[0];
    const void*  labels = d_in[1];
    float* out = (float*)d_out;
    long long osz = (long long)out_size;

    k1<<<64, 256>>>(labels);
    k2<<<65, 256>>>();
    k_main<<<BB, 256>>>(logits, out, osz);
}

// round 10
// speedup vs baseline: 1.3251x; 1.1322x over previous
#include <cuda_runtime.h>
#include <math.h>

#define BB 16384
#define CC 8192

// ---------------- device scratch (no runtime allocation) ----------------
// d_first2/d_cnt are ZERO when idle; k_main's final block re-zeroes them for
// the next graph replay. d_first2[lab] = max over rows i with label lab of
// (BB - i)  =>  first occurrence = BB - d_first2[lab]; 0 = label absent.
__device__ int   d_first2[CC];
__device__ int   d_cnt[CC];
__device__ int   d_hist[64 * CC];      // per-256-row-block histograms -> excl. block prefix
__device__ int   d_start[BB];          // excl. scan of group sizes (keyed by first-occ row)
__device__ int   d_rank[BB];           // stable rank within 256-row block (same label)
__device__ int   d_lab[BB];            // normalized int32 labels
__device__ float d_loss[BB];           // per-row loss
__device__ unsigned int d_ticket;      // last-block election in k_main

// ================= k1: detect + convert + count + stable in-block rank =================
__global__ void __launch_bounds__(256) k1(const void* __restrict__ labels) {
    const int t = threadIdx.x, b = blockIdx.x;
    __shared__ unsigned short srun[CC];   // 16KB running block histogram
    __shared__ int s_is64;

    // label width detection: int64 (LE) => all odd 32-bit words zero.
    // p < 8192 keeps word index valid for the int32 case too.
    {
        const int* w = (const int*)labels;
        int p = (b & 31) * 256 + t;
        int any = __syncthreads_or(w[2 * p + 1] != 0);
        if (t == 0) s_is64 = !any;
    }
    for (int k = t; k < CC; k += 256) srun[k] = 0;
    __syncthreads();

    const int i = b * 256 + t;
    const int lab = s_is64 ? (int)((const long long*)labels)[i]
                           : ((const int*)labels)[i];
    d_lab[i] = lab;
    atomicMax(&d_first2[lab], BB - i);     // zero-init friendly "first occurrence"
    atomicAdd(&d_cnt[lab], 1);

    // stable in-block rank via warp-ordered phases (u16 smem, no atomics)
    const int l = t & 31, w = t >> 5;
    unsigned eq = 0u;
#pragma unroll
    for (int j = 0; j < 32; j++) {
        int lj = __shfl_sync(0xffffffffu, lab, j);
        eq |= (unsigned)(lj == lab) << j;
    }
    const int before  = __popc(eq & ((1u << l) - 1u));
    const int total   = __popc(eq);
    const bool is_last = (31 - __clz(eq)) == l;
    int rank = 0;
    for (int ph = 0; ph < 8; ph++) {
        if (w == ph) {
            rank = (int)srun[lab] + before;
            __syncwarp();
            if (is_last) srun[lab] = (unsigned short)((int)srun[lab] + total);
        }
        __syncthreads();
    }
    d_rank[i] = rank;
    for (int k = t; k < CC; k += 256) d_hist[b * CC + k] = (int)srun[k];
}

// ================= k2: coalesced hist prefix (blocks 0-7) + group scan (block 8) =================
__global__ void __launch_bounds__(1024) k2() {
    const int t = threadIdx.x, b = blockIdx.x;
    if (b < 8) {
        // in-place exclusive prefix along the 64-block axis, one thread per
        // label column: consecutive threads -> consecutive addresses (coalesced)
        const int c = b * 1024 + t;
        int run = 0;
#pragma unroll 4
        for (int k = 0; k < 64; k++) {
            int v = d_hist[k * CC + c];
            d_hist[k * CC + c] = run;
            run += v;
        }
    } else {
        // exclusive scan of group sizes keyed by first-occurrence row
        __shared__ int sums[1024];
        const int base = t * 16;
        int local[16];
        int acc = 0;
#pragma unroll
        for (int k = 0; k < 16; k++) {
            int r = base + k;
            int lab = d_lab[r];
            int gv = (BB - d_first2[lab] == r) ? d_cnt[lab] : 0;
            local[k] = acc;
            acc += gv;
        }
        sums[t] = acc;
        __syncthreads();
        for (int off = 1; off < 1024; off <<= 1) {
            int v = (t >= off) ? sums[t - off] : 0;
            __syncthreads();
            sums[t] += v;
            __syncthreads();
        }
        int offset = (t == 0) ? 0 : sums[t - 1];
#pragma unroll
        for (int k = 0; k < 16; k++) d_start[base + k] = offset + local[k];
    }
}

// ================= main streaming kernel (proven 182us body) =================
__global__ void __launch_bounds__(256) k_main(const float* __restrict__ logits,
                                              float* __restrict__ out,
                                              long long osz) {
    const int row = blockIdx.x;
    const int t = threadIdx.x;
    const int lab = d_lab[row];
    const int dst = d_start[BB - d_first2[lab]]
                  + d_hist[(row >> 8) * CC + lab] + d_rank[row];
    const float4* __restrict__ src = (const float4*)(logits + (size_t)row * CC);
    float4* __restrict__ o4 = (float4*)(out + (size_t)dst * CC);

    const int tgt4 = lab >> 2, tsub = lab & 3;
    const long long nbig = (long long)BB * CC;
    const bool do_store = (osz >= nbig);

    float s0 = 0.0f, s1 = 0.0f;
    float tval = 0.0f;
    bool have_t = false;

#pragma unroll
    for (int k = 0; k < 8; k++) {
        const int idx = k * 256 + t;
        float4 x = __ldcs(src + idx);
        if (idx == tgt4) {
            float vv = (tsub == 0) ? x.x : (tsub == 1) ? x.y : (tsub == 2) ? x.z : x.w;
            float nv = (vv > 0.0f) ? (vv / 2.00001f - 0.2f) : (vv * 2.00001f - 0.2f);
            if (tsub == 0) x.x = nv; else if (tsub == 1) x.y = nv;
            else if (tsub == 2) x.z = nv; else x.w = nv;
            tval = nv; have_t = true;
        }
        if (do_store) __stcs(o4 + idx, x);
        s0 += __expf(x.x) + __expf(x.y);
        s1 += __expf(x.z) + __expf(x.w);
    }

    __shared__ float red[8];
    float ws = s0 + s1;
#pragma unroll
    for (int o = 16; o; o >>= 1) ws += __shfl_xor_sync(0xffffffffu, ws, o);
    if ((t & 31) == 0) red[t >> 5] = ws;
    __syncthreads();
    if (t < 32) {
        float v = (t < 8) ? red[t] : 0.0f;
#pragma unroll
        for (int o = 4; o; o >>= 1) v += __shfl_xor_sync(0xffffffffu, v, o);
        if (t == 0) red[0] = v;
    }
    __syncthreads();
    const float s = red[0];

    if (have_t) {
        d_loss[row] = __logf(s) - tval;
        __threadfence();                       // publish loss before ticket
    }
    if (t == 0 && osz >= nbig + BB) out[(size_t)nbig + dst] = (float)lab;

    // ---- last block: deterministic loss reduction + scratch reset for next replay ----
    __shared__ unsigned int s_last;
    __syncthreads();
    if (t == 0) s_last = atomicAdd(&d_ticket, 1u);
    __syncthreads();
    if (s_last == BB - 1) {
        __threadfence();
        __shared__ double sd[256];
        double a = 0.0;
        const float4* lf = (const float4*)d_loss;
        for (int i = t; i < BB / 4; i += 256) {
            float4 v = __ldcg(lf + i);
            a += (double)v.x + (double)v.y + (double)v.z + (double)v.w;
        }
        sd[t] = a;
        __syncthreads();
        for (int o = 128; o; o >>= 1) {
            if (t < o) sd[t] += sd[t + o];
            __syncthreads();
        }
        if (t == 0) {
            float L = (float)(sd[0] / (double)BB);
            if (osz >= nbig + BB + 1)      out[(size_t)nbig + BB] = L;
            else if (osz == 1)             out[0] = L;
            d_ticket = 0u;
        }
        // zero d_first2/d_cnt for the next replay (all blocks already past
        // their reads: every block incremented d_ticket after computing dst)
        for (int k = t; k < CC; k += 256) { d_first2[k] = 0; d_cnt[k] = 0; }
    }
}

// ---------------- launch ----------------
extern "C" void kernel_launch(void* const* d_in, const int* in_sizes, int n_in,
                              void* d_out, int out_size) {
    const float* logits = (const float*)d_in[0];
    const void*  labels = d_in[1];
    float* out = (float*)d_out;
    long long osz = (long long)out_size;

    k1<<<64, 256>>>(labels);
    k2<<<9, 1024>>>();
    k_main<<<BB, 256>>>(logits, out, osz);
}